// round 1
// baseline (speedup 1.0000x reference)
#include <cuda_runtime.h>
#include <math.h>

// Problem constants
#define BN_  512      // batch (docs)
#define VV   50000    // vocab
#define KK   200      // topics
#define HH   300      // embed dim
#define HIDD 800      // hidden

#define K1_SPLIT 6
#define K4_SPLIT 24
#define KT_TOTAL (VV/16)          // 3125
#define KT1_PER_Z ((KT_TOTAL + K1_SPLIT - 1)/K1_SPLIT)   // 521
#define KT4_PER_Z ((KT_TOTAL + K4_SPLIT - 1)/K4_SPLIT)   // 131

#define VT ((VV + 63)/64)         // 782 v-tiles
#define NPART (VT*8)              // 6256 partials for fwd/tm

// ---------------- scratch (device globals; no allocation allowed) ----------------
__device__ float g_hid[BN_*HIDD];
__device__ float g_theta[BN_*KK];
__device__ float g_tn[BN_*KK];
__device__ float g_theta2[BN_*KK];
__device__ float g_dis[VV*KK];
__device__ float g_colsum[BN_*KK];
__device__ float g_ntok[BN_];
__device__ float g_invn[BN_];
__device__ float g_S[KK];
__device__ float g_Spart[100*KK];
__device__ float g_part1[K1_SPLIT*BN_*HIDD];
__device__ float g_part4[K4_SPLIT*BN_*KK];
__device__ float g_partF[NPART];
__device__ float g_partT[NPART];
__device__ float g_partB[BN_];

__constant__ float c_lg[5] = {0.0f, 0.0f, 0.69314718055994531f,
                              1.79175946922805500f, 3.17805383034794562f};

// ---------------- n_tok per doc ----------------
__global__ void k_ntok(const float* __restrict__ bows) {
    int b = blockIdx.x, t = threadIdx.x;
    float s = 0.f;
    for (int v = t; v < VV; v += 256) s += bows[(size_t)b*VV + v];
    __shared__ float red[256];
    red[t] = s; __syncthreads();
    for (int st = 128; st > 0; st >>= 1) { if (t < st) red[t] += red[t+st]; __syncthreads(); }
    if (t == 0) { float n = red[0]; g_ntok[b] = n; g_invn[b] = (n > 0.f) ? 1.f/n : 0.f; }
}

// ---------------- GEMM A(M,K) @ B(K,N), split-K partials ----------------
// WHICH=0: hid partials (A=bows, B=W1, N=800), WHICH=1: colsum partials (A=bows, B=g_dis, N=200)
template<int WHICH>
__global__ void gemm_ab(const float* __restrict__ A, const float* __restrict__ Bp) {
    constexpr int M = BN_;
    constexpr int N = (WHICH == 0) ? HIDD : KK;
    constexpr int Kd = VV;
    constexpr int KTPZ = (WHICH == 0) ? KT1_PER_Z : KT4_PER_Z;
    const float* B = (WHICH == 0) ? Bp : (const float*)g_dis;
    float* Cpart = (WHICH == 0) ? g_part1 : g_part4;

    __shared__ __align__(16) float As[16][68];
    __shared__ __align__(16) float Bs[16][68];
    const int tid = threadIdx.x;
    const int tx = tid & 15, ty = tid >> 4;
    const int m0 = blockIdx.y * 64, n0 = blockIdx.x * 64;
    const int z = blockIdx.z;
    const int kt0 = z * KTPZ;
    const int kt1 = min(kt0 + KTPZ, KT_TOTAL);
    const int ar = tid >> 2, ac = (tid & 3) << 2;
    const int br = tid >> 4, bc = (tid & 15) << 2;

    float acc[4][4];
    #pragma unroll
    for (int i = 0; i < 4; i++)
        #pragma unroll
        for (int j = 0; j < 4; j++) acc[i][j] = 0.f;

    for (int kt = kt0; kt < kt1; ++kt) {
        int k0 = kt * 16;
        {   // A tile 64x16 (Kd % 16 == 0, m always < M=512)
            float4 v = *reinterpret_cast<const float4*>(A + (size_t)(m0+ar)*Kd + k0 + ac);
            As[ac+0][ar] = v.x; As[ac+1][ar] = v.y; As[ac+2][ar] = v.z; As[ac+3][ar] = v.w;
        }
        {   // B tile 16x64
            float4 v = make_float4(0.f,0.f,0.f,0.f);
            int gk = k0 + br, gn = n0 + bc;
            const float* bp = B + (size_t)gk*N + gn;
            if (gn + 3 < N) v = *reinterpret_cast<const float4*>(bp);
            else {
                if (gn + 0 < N) v.x = bp[0];
                if (gn + 1 < N) v.y = bp[1];
                if (gn + 2 < N) v.z = bp[2];
            }
            *reinterpret_cast<float4*>(&Bs[br][bc]) = v;
        }
        __syncthreads();
        #pragma unroll
        for (int k = 0; k < 16; k++) {
            float4 a = *reinterpret_cast<const float4*>(&As[k][ty << 2]);
            float4 b = *reinterpret_cast<const float4*>(&Bs[k][tx << 2]);
            float av[4] = {a.x, a.y, a.z, a.w};
            float bv[4] = {b.x, b.y, b.z, b.w};
            #pragma unroll
            for (int i = 0; i < 4; i++)
                #pragma unroll
                for (int j = 0; j < 4; j++)
                    acc[i][j] = fmaf(av[i], bv[j], acc[i][j]);
        }
        __syncthreads();
    }

    float* Cz = Cpart + (size_t)z * M * N;
    #pragma unroll
    for (int i = 0; i < 4; i++) {
        int m = m0 + (ty << 2) + i;          // < 512 always
        int n = n0 + (tx << 2);
        float* row = Cz + (size_t)m*N + n;
        if (n + 3 < N)
            *reinterpret_cast<float4*>(row) = make_float4(acc[i][0], acc[i][1], acc[i][2], acc[i][3]);
        else {
            #pragma unroll
            for (int j = 0; j < 4; j++) if (n + j < N) row[j] = acc[i][j];
        }
    }
}

__global__ void k1_reduce(const float* __restrict__ b1) {
    int idx = blockIdx.x * 256 + threadIdx.x;
    if (idx >= BN_*HIDD) return;
    float s = 0.f;
    #pragma unroll
    for (int z = 0; z < K1_SPLIT; z++) s += g_part1[(size_t)z*BN_*HIDD + idx];
    g_hid[idx] = fmaxf(s + b1[idx % HIDD], 0.f);
}

__global__ void k4_reduce() {
    int idx = blockIdx.x * 256 + threadIdx.x;
    if (idx >= BN_*KK) return;
    float s = 0.f;
    #pragma unroll
    for (int z = 0; z < K4_SPLIT; z++) s += g_part4[(size_t)z*BN_*KK + idx];
    g_colsum[idx] = s;
}

// ---------------- theta = softplus(hid@W2+b2); tn = softmax(theta) ----------------
__global__ void k_theta(const float* __restrict__ W2, const float* __restrict__ b2) {
    int b = blockIdx.x, t = threadIdx.x;
    __shared__ float sh[HIDD];
    __shared__ float red[256];
    for (int h = t; h < HIDD; h += 256) sh[h] = g_hid[(size_t)b*HIDD + h];
    __syncthreads();
    float th = -1e30f;
    if (t < KK) {
        float acc = b2[t];
        #pragma unroll 4
        for (int h = 0; h < HIDD; h++) acc = fmaf(sh[h], W2[(size_t)h*KK + t], acc);
        th = fmaxf(acc, 0.f) + log1pf(expf(-fabsf(acc)));   // softplus = logaddexp(x,0)
        g_theta[(size_t)b*KK + t] = th;
    }
    red[t] = th; __syncthreads();
    for (int s = 128; s > 0; s >>= 1) { if (t < s) red[t] = fmaxf(red[t], red[t+s]); __syncthreads(); }
    float mx = red[0]; __syncthreads();
    float e = (t < KK) ? expf(th - mx) : 0.f;
    red[t] = e; __syncthreads();
    for (int s = 128; s > 0; s >>= 1) { if (t < s) red[t] += red[t+s]; __syncthreads(); }
    float sm = red[0];
    if (t < KK) g_tn[(size_t)b*KK + t] = e / sm;
}

// ---------------- GEMM C = A(M,Kd) @ B(N,Kd)^T with fused epilogues ----------------
// EPI=0: inner=rho@alpha^T -> dis=clip(exp(inner))       (M=VV, N=KK, Kd=HH)
// EPI=1: den^T = tn@dis^T, fused forward reduction       (M=BN_, N=VV, Kd=KK)
// EPI=2: recon = theta2@dis^T, fused Poisson reduction   (M=BN_, N=VV, Kd=KK)
template<int EPI>
__global__ void gemm_abt(const float* __restrict__ Ain, const float* __restrict__ Bin,
                         const float* __restrict__ bows) {
    constexpr int M  = (EPI == 0) ? VV : BN_;
    constexpr int N  = (EPI == 0) ? KK : VV;
    constexpr int Kd = (EPI == 0) ? HH : KK;
    const float* A = (EPI == 0) ? Ain : ((EPI == 1) ? (const float*)g_tn : (const float*)g_theta2);
    const float* B = (EPI == 0) ? Bin : (const float*)g_dis;

    __shared__ __align__(16) float As[16][68];
    __shared__ __align__(16) float Bs[16][68];
    const int tid = threadIdx.x;
    const int tx = tid & 15, ty = tid >> 4;
    const int m0 = blockIdx.y * 64, n0 = blockIdx.x * 64;
    const int ar = tid >> 2, ac = (tid & 3) << 2;
    constexpr int ktTotal = (Kd + 15) / 16;

    float acc[4][4];
    #pragma unroll
    for (int i = 0; i < 4; i++)
        #pragma unroll
        for (int j = 0; j < 4; j++) acc[i][j] = 0.f;

    for (int kt = 0; kt < ktTotal; ++kt) {
        int k0 = kt * 16;
        {   // A tile (rows m, cols k) -> transposed
            float4 v = make_float4(0.f,0.f,0.f,0.f);
            int gm = m0 + ar, gk = k0 + ac;
            if (gm < M) {
                const float* p = A + (size_t)gm*Kd + gk;
                if (gk + 3 < Kd) v = *reinterpret_cast<const float4*>(p);
                else {
                    if (gk + 0 < Kd) v.x = p[0];
                    if (gk + 1 < Kd) v.y = p[1];
                    if (gk + 2 < Kd) v.z = p[2];
                }
            }
            As[ac+0][ar] = v.x; As[ac+1][ar] = v.y; As[ac+2][ar] = v.z; As[ac+3][ar] = v.w;
        }
        {   // B tile (rows n, cols k) -> transposed
            float4 v = make_float4(0.f,0.f,0.f,0.f);
            int gn = n0 + ar, gk = k0 + ac;
            if (gn < N) {
                const float* p = B + (size_t)gn*Kd + gk;
                if (gk + 3 < Kd) v = *reinterpret_cast<const float4*>(p);
                else {
                    if (gk + 0 < Kd) v.x = p[0];
                    if (gk + 1 < Kd) v.y = p[1];
                    if (gk + 2 < Kd) v.z = p[2];
                }
            }
            Bs[ac+0][ar] = v.x; Bs[ac+1][ar] = v.y; Bs[ac+2][ar] = v.z; Bs[ac+3][ar] = v.w;
        }
        __syncthreads();
        #pragma unroll
        for (int k = 0; k < 16; k++) {
            float4 a = *reinterpret_cast<const float4*>(&As[k][ty << 2]);
            float4 b = *reinterpret_cast<const float4*>(&Bs[k][tx << 2]);
            float av[4] = {a.x, a.y, a.z, a.w};
            float bv[4] = {b.x, b.y, b.z, b.w};
            #pragma unroll
            for (int i = 0; i < 4; i++)
                #pragma unroll
                for (int j = 0; j < 4; j++)
                    acc[i][j] = fmaf(av[i], bv[j], acc[i][j]);
        }
        __syncthreads();
    }

    if constexpr (EPI == 0) {
        #pragma unroll
        for (int i = 0; i < 4; i++) {
            int m = m0 + (ty << 2) + i;
            if (m >= M) continue;
            int n = n0 + (tx << 2);
            float o[4];
            #pragma unroll
            for (int j = 0; j < 4; j++)
                o[j] = fminf(fmaxf(expf(acc[i][j]), 1e-30f), 1e10f);
            float* row = g_dis + (size_t)m*N + n;
            if (n + 3 < N) *reinterpret_cast<float4*>(row) = make_float4(o[0], o[1], o[2], o[3]);
            else { 
                #pragma unroll
                for (int j = 0; j < 4; j++) if (n + j < N) row[j] = o[j];
            }
        }
    } else {
        float local = 0.f;
        #pragma unroll
        for (int i = 0; i < 4; i++) {
            int b = m0 + (ty << 2) + i;          // doc index (< 512 always)
            int v0 = n0 + (tx << 2);
            float wv[4] = {0.f, 0.f, 0.f, 0.f};
            if (v0 + 3 < VV) {
                float4 w4 = *reinterpret_cast<const float4*>(bows + (size_t)b*VV + v0);
                wv[0] = w4.x; wv[1] = w4.y; wv[2] = w4.z; wv[3] = w4.w;
            } else {
                #pragma unroll
                for (int j = 0; j < 4; j++) if (v0 + j < VV) wv[j] = bows[(size_t)b*VV + v0 + j];
            }
            if constexpr (EPI == 1) {
                float inv = g_invn[b];
                #pragma unroll
                for (int j = 0; j < 4; j++) {
                    if (v0 + j < VV && wv[j] != 0.f)
                        local += __fdividef(wv[j] * inv, acc[i][j] + 1e-30f);
                }
            } else {
                #pragma unroll
                for (int j = 0; j < 4; j++) {
                    if (v0 + j >= VV) continue;
                    float r = acc[i][j];
                    float w = wv[j];
                    if (w == 0.f) { local += r; }
                    else {
                        int ib = (int)w;
                        float lg = (ib >= 0 && ib < 5 && (float)ib == w) ? c_lg[ib] : lgammaf(w + 1.f);
                        local += r + lg - w * __logf(r + 1e-10f);
                    }
                }
            }
        }
        __shared__ float red[256];
        red[tid] = local; __syncthreads();
        for (int s = 128; s > 0; s >>= 1) { if (tid < s) red[tid] += red[tid+s]; __syncthreads(); }
        if (tid == 0) {
            float* dst = (EPI == 1) ? g_partF : g_partT;
            dst[blockIdx.y * gridDim.x + blockIdx.x] = red[0];
        }
    }
}

// ---------------- phi denominators S_k = sum_v dis[v,k] ----------------
__global__ void k_spart() {
    int t = threadIdx.x;
    if (t >= KK) return;
    int v0 = blockIdx.x * 500;
    float s = 0.f;
    for (int v = v0; v < v0 + 500; v++) s += g_dis[(size_t)v*KK + t];
    g_Spart[blockIdx.x*KK + t] = s;
}
__global__ void k_sreduce() {
    int t = threadIdx.x;
    if (t < KK) {
        float s = 0.f;
        for (int i = 0; i < 100; i++) s += g_Spart[i*KK + t];
        g_S[t] = s;
    }
}
__global__ void k_theta2() {
    int idx = blockIdx.x * 256 + threadIdx.x;
    if (idx >= BN_*KK) return;
    g_theta2[idx] = g_theta[idx] / g_S[idx % KK];
}

// ---------------- backward cost per doc ----------------
__global__ void k_bwd() {
    int b = blockIdx.x, t = threadIdx.x;
    float local = 0.f;
    if (t < KK) {
        float cs = g_colsum[(size_t)b*KK + t];
        local = g_ntok[b] * g_tn[(size_t)b*KK + t] / (cs + 1e-30f);
    }
    __shared__ float red[256];
    red[t] = local; __syncthreads();
    for (int s = 128; s > 0; s >>= 1) { if (t < s) red[t] += red[t+s]; __syncthreads(); }
    if (t == 0) g_partB[b] = red[0];
}

// ---------------- final deterministic reductions + scaling ----------------
__global__ void k_final(float* __restrict__ out) {
    int t = threadIdx.x;
    __shared__ double red[256];

    double s = 0.0;
    for (int i = t; i < NPART; i += 256) s += (double)g_partF[i];
    red[t] = s; __syncthreads();
    for (int st = 128; st > 0; st >>= 1) { if (t < st) red[t] += red[t+st]; __syncthreads(); }
    double fwd = red[0]; __syncthreads();

    s = 0.0;
    for (int i = t; i < NPART; i += 256) s += (double)g_partT[i];
    red[t] = s; __syncthreads();
    for (int st = 128; st > 0; st >>= 1) { if (t < st) red[t] += red[t+st]; __syncthreads(); }
    double tmsum = red[0]; __syncthreads();

    s = 0.0;
    for (int i = t; i < BN_; i += 256) s += (double)g_partB[i];
    red[t] = s; __syncthreads();
    for (int st = 128; st > 0; st >>= 1) { if (t < st) red[t] += red[t+st]; __syncthreads(); }
    double bwd = red[0];

    if (t == 0) {
        out[0] = (float)(1.0 * (tmsum / (double)BN_));   // EPSILON * tm
        out[1] = (float)(0.5 * fwd);                     // BETA * forward
        out[2] = (float)(0.5 * bwd);                     // (1-BETA) * backward
    }
}

// ---------------- launch ----------------
extern "C" void kernel_launch(void* const* d_in, const int* in_sizes, int n_in,
                              void* d_out, int out_size) {
    const float* bows  = (const float*)d_in[0];
    const float* rho   = (const float*)d_in[1];
    const float* alpha = (const float*)d_in[2];
    const float* W1    = (const float*)d_in[3];
    const float* b1    = (const float*)d_in[4];
    const float* W2    = (const float*)d_in[5];
    const float* b2    = (const float*)d_in[6];
    float* out = (float*)d_out;

    // doc token counts
    k_ntok<<<BN_, 256>>>(bows);

    // hid = relu(bows@W1 + b1)   (split-K 6)
    gemm_ab<0><<<dim3(13, 8, K1_SPLIT), 256>>>(bows, W1);
    k1_reduce<<<(BN_*HIDD)/256, 256>>>(b1);

    // theta, theta_norm
    k_theta<<<BN_, 256>>>(W2, b2);

    // dis = clip(exp(rho@alpha^T))
    gemm_abt<0><<<dim3(4, VT), 256>>>(rho, alpha, nullptr);

    // S_k, theta2 = theta / S
    k_spart<<<100, 256>>>();
    k_sreduce<<<1, 256>>>();
    k_theta2<<<(BN_*KK + 255)/256, 256>>>();

    // colsum = bows@dis   (split-K 24)
    gemm_ab<1><<<dim3(4, 8, K4_SPLIT), 256>>>(bows, nullptr);
    k4_reduce<<<(BN_*KK + 255)/256, 256>>>();

    // backward cost partials
    k_bwd<<<BN_, 256>>>();

    // forward cost: den = tn@dis^T fused reduction
    gemm_abt<1><<<dim3(VT, 8), 256>>>(nullptr, nullptr, bows);

    // tm cost: recon = theta2@dis^T fused Poisson reduction
    gemm_abt<2><<<dim3(VT, 8), 256>>>(nullptr, nullptr, bows);

    // final scalars
    k_final<<<1, 256>>>(out);
}